// round 1
// baseline (speedup 1.0000x reference)
#include <cuda_runtime.h>

#define POOL 7
#define FW 128
#define FC 1024

__global__ __launch_bounds__(256, 8)
void roi_bilinear_kernel(const float* __restrict__ feat,
                         const float* __restrict__ rois,
                         float* __restrict__ out) {
    const int cell = blockIdx.x;          // 0..48  (py*7+px)
    const int roi  = blockIdx.y;          // 0..511
    const int py = cell / POOL;
    const int px = cell % POOL;

    // ROI box (float -> int32 truncation matches jnp astype(int32) on non-negative values)
    const float4 r = __ldg(((const float4*)rois) + roi);
    const int ymin = (int)r.x;
    const int xmin = (int)r.y;
    const int ymax = (int)r.z;
    const int xmax = (int)r.w;

    const float h = (float)(ymax - ymin + 1);
    const float w = (float)(xmax - xmin + 1);

    // match reference: grid * (h / P)
    const float sy = (float)py * (h / (float)POOL);
    const float sx = (float)px * (w / (float)POOL);

    const int y0 = (int)floorf(sy);
    const int x0 = (int)floorf(sx);
    const int y1 = min(y0 + 1, ymax - ymin);
    const int x1 = min(x0 + 1, xmax - xmin);

    const float fy = sy - (float)y0;
    const float fx = sx - (float)x0;

    const int gy0 = ymin + y0;
    const int gy1 = ymin + y1;
    const int gx0 = xmin + x0;
    const int gx1 = xmin + x1;

    const float4* __restrict__ p00 = (const float4*)(feat + ((size_t)gy0 * FW + gx0) * FC);
    const float4* __restrict__ p01 = (const float4*)(feat + ((size_t)gy0 * FW + gx1) * FC);
    const float4* __restrict__ p10 = (const float4*)(feat + ((size_t)gy1 * FW + gx0) * FC);
    const float4* __restrict__ p11 = (const float4*)(feat + ((size_t)gy1 * FW + gx1) * FC);

    const int c = threadIdx.x;            // 0..255, one float4 each (1024 ch / 4)

    const float4 tl = __ldg(p00 + c);
    const float4 tr = __ldg(p01 + c);
    const float4 bl = __ldg(p10 + c);
    const float4 br = __ldg(p11 + c);

    float4 o;
    {
        float top, bot;
        top = tl.x + (tr.x - tl.x) * fx;
        bot = bl.x + (br.x - bl.x) * fx;
        o.x = top + (bot - top) * fy;
        top = tl.y + (tr.y - tl.y) * fx;
        bot = bl.y + (br.y - bl.y) * fx;
        o.y = top + (bot - top) * fy;
        top = tl.z + (tr.z - tl.z) * fx;
        bot = bl.z + (br.z - bl.z) * fx;
        o.z = top + (bot - top) * fy;
        top = tl.w + (tr.w - tl.w) * fx;
        bot = bl.w + (br.w - bl.w) * fx;
        o.w = top + (bot - top) * fy;
    }

    float4* __restrict__ optr = (float4*)(out + ((size_t)roi * (POOL * POOL) + cell) * FC);
    optr[c] = o;
}

extern "C" void kernel_launch(void* const* d_in, const int* in_sizes, int n_in,
                              void* d_out, int out_size) {
    const float* feat = (const float*)d_in[0];   // (1,128,128,1024) fp32
    const float* rois = (const float*)d_in[1];   // (512,4) fp32
    float* out = (float*)d_out;                  // (512, 7*7*1024) fp32

    dim3 grid(POOL * POOL, 512);
    roi_bilinear_kernel<<<grid, 256>>>(feat, rois, out);
}